// round 2
// baseline (speedup 1.0000x reference)
#include <cuda_runtime.h>
#include <cstdint>

#define T_LEN 16384
#define HID   256
#define EMB   16
#define TMP   128
#define EVD   2048
#define NCTA  8
#define NEG_SLOPE 0.01f

// Scratch (static device globals — no allocation at runtime)
__device__ float g_X[T_LEN * TMP];   // 8 MB: bilstm part of layer-1 preactivation (incl. b1)
__device__ float g_C[EVD * TMP];     // 1 MB: event-embedding part of layer-1 preactivation
__device__ int   g_idx[T_LEN];       // argmax index emitted at each step

// Packed fp32x2 FMA (sm_100+): d = a*b + c elementwise on two packed floats.
__device__ __forceinline__ unsigned long long fma2(unsigned long long a,
                                                   unsigned long long b,
                                                   unsigned long long c) {
    unsigned long long d;
    asm("fma.rn.f32x2 %0, %1, %2, %3;" : "=l"(d) : "l"(a), "l"(b), "l"(c));
    return d;
}
__device__ __forceinline__ float2 unpack2(unsigned long long v) {
    float2 r;
    asm("mov.b64 {%0, %1}, %2;" : "=f"(r.x), "=f"(r.y) : "l"(v));
    return r;
}

// ---------------------------------------------------------------------------
// Phase 1a: X[t][j] = dot(bilstm[t, 0:256], W1[j, 0:256]) + b1[j]
// ---------------------------------------------------------------------------
__global__ void __launch_bounds__(128) x_kernel(const float* __restrict__ bilstm,
                                                const float* __restrict__ W1,
                                                const float* __restrict__ b1) {
    __shared__ __align__(16) float row[HID];
    const int t = blockIdx.x;
    const int j = threadIdx.x;
    row[j]       = bilstm[t * HID + j];
    row[j + 128] = bilstm[t * HID + 128 + j];
    __syncthreads();

    const float4* w4 = reinterpret_cast<const float4*>(W1 + j * (HID + EMB));
    const float4* r4 = reinterpret_cast<const float4*>(row);
    float a0 = 0.f, a1 = 0.f, a2 = 0.f, a3 = 0.f;
#pragma unroll
    for (int k = 0; k < HID / 4; k++) {
        float4 w = w4[k];
        float4 h = r4[k];
        a0 += w.x * h.x; a1 += w.y * h.y; a2 += w.z * h.z; a3 += w.w * h.w;
    }
    g_X[t * TMP + j] = (a0 + a1) + (a2 + a3) + b1[j];
}

// ---------------------------------------------------------------------------
// Phase 1b: C[e][j] = dot(emb_table[e, :], W1[j, 256:272])
// ---------------------------------------------------------------------------
__global__ void __launch_bounds__(128) c_kernel(const float* __restrict__ emb,
                                                const float* __restrict__ W1) {
    __shared__ __align__(16) float e[EMB];
    const int ei = blockIdx.x;
    const int j  = threadIdx.x;
    if (j < EMB) e[j] = emb[ei * EMB + j];
    __syncthreads();

    const float4* w4 = reinterpret_cast<const float4*>(W1 + j * (HID + EMB) + HID);
    const float4* e4 = reinterpret_cast<const float4*>(e);
    float a = 0.f;
#pragma unroll
    for (int k = 0; k < EMB / 4; k++) {
        float4 w = w4[k];
        float4 h = e4[k];
        a += w.x * h.x + w.y * h.y + w.z * h.z + w.w * h.w;
    }
    g_C[ei * TMP + j] = a;
}

// ---------------------------------------------------------------------------
// Phase 2: sequential greedy decode. Cluster of 8 CTAs x 256 threads.
// Packed f32x2 GEMV; argmax exchange via push-multicast DSMEM stores and
// per-CTA mbarrier (no full cluster barrier in the loop).
// ---------------------------------------------------------------------------
__global__ void __cluster_dims__(NCTA, 1, 1) __launch_bounds__(256, 1)
seq_kernel(const float* __restrict__ W2, const float* __restrict__ b2,
           const int* __restrict__ initp) {
    __shared__ __align__(16) float sh_h[TMP];
    __shared__ unsigned long long sh_warp[8];
    __shared__ __align__(8) unsigned long long cand[2][NCTA];  // [step parity][source rank]
    __shared__ __align__(8) unsigned long long mbar[2];        // double-buffered mbarriers
    __shared__ int sh_bcast;

    unsigned rank;
    asm("mov.u32 %0, %%cluster_ctarank;" : "=r"(rank));
    const int tid  = threadIdx.x;
    const int lane = tid & 31;
    const int wid  = tid >> 5;
    const int r    = (int)rank * 256 + tid;   // this thread's logit row

    // Pin W2 row as 64 packed f32x2 registers + bias.
    unsigned long long w[TMP / 2];
    const unsigned long long* wp =
        reinterpret_cast<const unsigned long long*>(W2 + (size_t)r * TMP);
#pragma unroll
    for (int k = 0; k < TMP / 2; k++) w[k] = wp[k];
    const float bias = b2[r];

    if (tid == 0) {
        unsigned m0 = (unsigned)__cvta_generic_to_shared(&mbar[0]);
        unsigned m1 = (unsigned)__cvta_generic_to_shared(&mbar[1]);
        asm volatile("mbarrier.init.shared.b64 [%0], %1;" :: "r"(m0), "r"(NCTA) : "memory");
        asm volatile("mbarrier.init.shared.b64 [%0], %1;" :: "r"(m1), "r"(NCTA) : "memory");
        asm volatile("fence.mbarrier_init.release.cluster;" ::: "memory");
    }
    __syncthreads();
    asm volatile("barrier.cluster.arrive.aligned;" ::: "memory");
    asm volatile("barrier.cluster.wait.aligned;" ::: "memory");

    int idx = *initp;
    float xv = (tid < TMP) ? g_X[tid] : 0.f;

    for (int t = 0; t < T_LEN; t++) {
        // h = leaky(X[t] + C[idx])
        if (tid < TMP) {
            float v = xv + g_C[idx * TMP + tid];
            sh_h[tid] = (v > 0.f) ? v : NEG_SLOPE * v;
        }
        // prefetch next X row (idx-independent)
        float xn = 0.f;
        if (tid < TMP && t + 1 < T_LEN) xn = g_X[(t + 1) * TMP + tid];
        __syncthreads();

        // GEMV: logit = W2[r] . h + b2[r]  (packed f32x2, 4 independent chains)
        const ulonglong2* h16 = reinterpret_cast<const ulonglong2*>(sh_h);
        unsigned long long a0 = 0ull, a1 = 0ull, a2 = 0ull, a3 = 0ull;
#pragma unroll
        for (int k = 0; k < 32; k += 2) {
            ulonglong2 hA = h16[k];
            ulonglong2 hB = h16[k + 1];
            a0 = fma2(w[2 * k + 0], hA.x, a0);
            a1 = fma2(w[2 * k + 1], hA.y, a1);
            a2 = fma2(w[2 * k + 2], hB.x, a2);
            a3 = fma2(w[2 * k + 3], hB.y, a3);
        }
        float2 f0 = unpack2(a0), f1 = unpack2(a1), f2v = unpack2(a2), f3 = unpack2(a3);
        const float acc = bias + (((f0.x + f0.y) + (f1.x + f1.y)) +
                                  ((f2v.x + f2v.y) + (f3.x + f3.y)));

        // warp argmax: monotone float->uint key; tie -> lowest global row
        unsigned key = __float_as_uint(acc);
        key ^= (key & 0x80000000u) ? 0xFFFFFFFFu : 0x80000000u;
        const unsigned wmax = __reduce_max_sync(0xFFFFFFFFu, key);
        const unsigned ball = __ballot_sync(0xFFFFFFFFu, key == wmax);
        if (lane == 0) {
            const int rwin = (int)rank * 256 + wid * 32 + (__ffs(ball) - 1);
            sh_warp[wid] = ((unsigned long long)wmax << 32) | (unsigned)(2047 - rwin);
        }
        __syncthreads();

        const int p  = t & 1;
        const int ph = (t >> 1) & 1;
        if (wid == 0) {
            // CTA-level reduce across the 8 warp candidates (lanes 0-7 active groups)
            unsigned long long v = (lane < 8) ? sh_warp[lane] : 0ull;
            { unsigned long long o = __shfl_xor_sync(0xFFFFFFFFu, v, 4); v = (o > v) ? o : v; }
            { unsigned long long o = __shfl_xor_sync(0xFFFFFFFFu, v, 2); v = (o > v) ? o : v; }
            { unsigned long long o = __shfl_xor_sync(0xFFFFFFFFu, v, 1); v = (o > v) ? o : v; }

            // push candidate to every rank's cand[p][myrank] + arrive their mbar[p]
            if (lane < NCTA) {
                unsigned lc = (unsigned)__cvta_generic_to_shared(&cand[p][rank]);
                unsigned rc;
                asm("mapa.shared::cluster.u32 %0, %1, %2;" : "=r"(rc) : "r"(lc), "r"(lane));
                asm volatile("st.shared::cluster.u64 [%0], %1;" :: "r"(rc), "l"(v) : "memory");
                unsigned lm = (unsigned)__cvta_generic_to_shared(&mbar[p]);
                unsigned rm;
                asm("mapa.shared::cluster.u32 %0, %1, %2;" : "=r"(rm) : "r"(lm), "r"(lane));
                asm volatile("mbarrier.arrive.release.cluster.shared::cluster.b64 _, [%0];"
                             :: "r"(rm) : "memory");
            }

            // wait local mbar[p] for this buffer's phase
            {
                unsigned lm = (unsigned)__cvta_generic_to_shared(&mbar[p]);
                asm volatile(
                    "{\n\t.reg .pred P1;\n\t"
                    "LW%=:\n\t"
                    "mbarrier.try_wait.parity.acquire.cluster.shared::cta.b64 P1, [%0], %1, 0x989680;\n\t"
                    "@P1 bra.uni LD%=;\n\t"
                    "bra.uni LW%=;\n\t"
                    "LD%=:\n\t}"
                    :: "r"(lm), "r"(ph) : "memory");
            }

            // reduce the 8 received candidates locally
            unsigned long long c = (lane < 8) ? cand[p][lane] : 0ull;
            { unsigned long long o = __shfl_xor_sync(0xFFFFFFFFu, c, 4); c = (o > c) ? o : c; }
            { unsigned long long o = __shfl_xor_sync(0xFFFFFFFFu, c, 2); c = (o > c) ? o : c; }
            { unsigned long long o = __shfl_xor_sync(0xFFFFFFFFu, c, 1); c = (o > c) ? o : c; }
            if (lane == 0) {
                const int win = 2047 - (int)(c & 0xFFFFFFFFull);
                sh_bcast = win;
                if (rank == 0) g_idx[t] = win;
            }
        }
        __syncthreads();
        idx = sh_bcast;
        xv  = xn;
    }
}

// ---------------------------------------------------------------------------
// Phase 3: recompute logits for all t (8 rows per CTA, 4 cols per thread,
// packed f32x2), log_softmax, write all three outputs:
// [T*2048 log_probs | T*16 emb | T index-as-float].
// ---------------------------------------------------------------------------
__global__ void __launch_bounds__(512) out_kernel(const float* __restrict__ W2,
                                                  const float* __restrict__ b2,
                                                  const float* __restrict__ emb,
                                                  const int* __restrict__ initp,
                                                  float* __restrict__ out) {
    __shared__ __align__(16) float sh_h[8][TMP];
    __shared__ float red[16];
    const int t0  = blockIdx.x * 8;
    const int tid = threadIdx.x;
    const int lane = tid & 31;
    const int wid  = tid >> 5;

    // rebuild h rows exactly as in seq_kernel
    for (int q = tid; q < 8 * TMP; q += 512) {
        const int rr = q >> 7, j = q & 127;
        const int t = t0 + rr;
        const int in_idx = (t == 0) ? *initp : g_idx[t - 1];
        float v = g_X[t * TMP + j] + g_C[in_idx * TMP + j];
        sh_h[rr][j] = (v > 0.f) ? v : NEG_SLOPE * v;
    }
    __syncthreads();

    unsigned long long acc[8][4];
#pragma unroll
    for (int rr = 0; rr < 8; rr++)
#pragma unroll
        for (int cj = 0; cj < 4; cj++) acc[rr][cj] = 0ull;

    const ulonglong2* W16 = reinterpret_cast<const ulonglong2*>(W2);
#pragma unroll 2
    for (int k = 0; k < 32; k++) {
        ulonglong2 hh[8];
#pragma unroll
        for (int rr = 0; rr < 8; rr++)
            hh[rr] = reinterpret_cast<const ulonglong2*>(sh_h[rr])[k];
#pragma unroll
        for (int cj = 0; cj < 4; cj++) {
            const int c = tid + 512 * cj;
            const ulonglong2 wv = W16[(size_t)c * 32 + k];
#pragma unroll
            for (int rr = 0; rr < 8; rr++) {
                acc[rr][cj] = fma2(wv.x, hh[rr].x, acc[rr][cj]);
                acc[rr][cj] = fma2(wv.y, hh[rr].y, acc[rr][cj]);
            }
        }
    }

    float logit[8][4];
#pragma unroll
    for (int cj = 0; cj < 4; cj++) {
        const float b = b2[tid + 512 * cj];
#pragma unroll
        for (int rr = 0; rr < 8; rr++) {
            float2 f = unpack2(acc[rr][cj]);
            logit[rr][cj] = f.x + f.y + b;
        }
    }

    // log_softmax per row, then write
    for (int rr = 0; rr < 8; rr++) {
        float m = logit[rr][0];
#pragma unroll
        for (int cj = 1; cj < 4; cj++) m = fmaxf(m, logit[rr][cj]);
#pragma unroll
        for (int o = 16; o > 0; o >>= 1) m = fmaxf(m, __shfl_xor_sync(0xFFFFFFFFu, m, o));
        if (lane == 0) red[wid] = m;
        __syncthreads();
        float M = red[0];
#pragma unroll
        for (int i = 1; i < 16; i++) M = fmaxf(M, red[i]);
        __syncthreads();

        float s = 0.f;
#pragma unroll
        for (int cj = 0; cj < 4; cj++) s += __expf(logit[rr][cj] - M);
#pragma unroll
        for (int o = 16; o > 0; o >>= 1) s += __shfl_xor_sync(0xFFFFFFFFu, s, o);
        if (lane == 0) red[wid] = s;
        __syncthreads();
        float S = 0.f;
#pragma unroll
        for (int i = 0; i < 16; i++) S += red[i];
        __syncthreads();

        const float lse = M + __logf(S);
        const int t = t0 + rr;
#pragma unroll
        for (int cj = 0; cj < 4; cj++)
            out[(size_t)t * EVD + tid + 512 * cj] = logit[rr][cj] - lse;
    }

    // ner_emb and ner_index outputs
    float* out_emb = out + (size_t)T_LEN * EVD;
    float* out_idx = out_emb + (size_t)T_LEN * EMB;
    if (tid < 8 * EMB) {
        const int rr = tid >> 4, j = tid & 15;
        const int t = t0 + rr;
        out_emb[t * EMB + j] = emb[g_idx[t] * EMB + j];
    }
    if (tid < 8) {
        const int t = t0 + tid;
        out_idx[t] = (float)g_idx[t];
    }
}

// ---------------------------------------------------------------------------
extern "C" void kernel_launch(void* const* d_in, const int* in_sizes, int n_in,
                              void* d_out, int out_size) {
    const float* bilstm = (const float*)d_in[0];
    const float* emb    = (const float*)d_in[1];
    const float* W1     = (const float*)d_in[2];
    const float* b1     = (const float*)d_in[3];
    const float* W2     = (const float*)d_in[4];
    const float* b2     = (const float*)d_in[5];
    const int*   init   = (const int*)d_in[6];
    float* out = (float*)d_out;

    x_kernel<<<T_LEN, 128>>>(bilstm, W1, b1);
    c_kernel<<<EVD, 128>>>(emb, W1);
    seq_kernel<<<NCTA, 256>>>(W2, b2, init);
    out_kernel<<<T_LEN / 8, 512>>>(W2, b2, emb, init, out);
}

// round 3
// speedup vs baseline: 1.5156x; 1.5156x over previous
#include <cuda_runtime.h>
#include <cstdint>

#define T_LEN 16384
#define HID   256
#define EMB   16
#define TMP   128
#define EVD   2048
#define NCTA  8
#define NEG_SLOPE 0.01f

// Scratch (static device globals — no allocation at runtime)
__device__ float g_X[T_LEN * TMP];   // 8 MB: bilstm part of layer-1 preactivation (incl. b1)
__device__ float g_C[EVD * TMP];     // 1 MB: event-embedding part of layer-1 preactivation
__device__ int   g_idx[T_LEN];       // argmax index emitted at each step

// Packed fp32x2 FMA (sm_100+): d = a*b + c elementwise on two packed floats.
__device__ __forceinline__ unsigned long long fma2(unsigned long long a,
                                                   unsigned long long b,
                                                   unsigned long long c) {
    unsigned long long d;
    asm("fma.rn.f32x2 %0, %1, %2, %3;" : "=l"(d) : "l"(a), "l"(b), "l"(c));
    return d;
}
__device__ __forceinline__ float2 unpack2(unsigned long long v) {
    float2 r;
    asm("mov.b64 {%0, %1}, %2;" : "=f"(r.x), "=f"(r.y) : "l"(v));
    return r;
}

// ---------------------------------------------------------------------------
// Phase 1a: X[t][j] = dot(bilstm[t, 0:256], W1[j, 0:256]) + b1[j]
// ---------------------------------------------------------------------------
__global__ void __launch_bounds__(128) x_kernel(const float* __restrict__ bilstm,
                                                const float* __restrict__ W1,
                                                const float* __restrict__ b1) {
    __shared__ __align__(16) float row[HID];
    const int t = blockIdx.x;
    const int j = threadIdx.x;
    row[j]       = bilstm[t * HID + j];
    row[j + 128] = bilstm[t * HID + 128 + j];
    __syncthreads();

    const float4* w4 = reinterpret_cast<const float4*>(W1 + j * (HID + EMB));
    const float4* r4 = reinterpret_cast<const float4*>(row);
    float a0 = 0.f, a1 = 0.f, a2 = 0.f, a3 = 0.f;
#pragma unroll
    for (int k = 0; k < HID / 4; k++) {
        float4 w = w4[k];
        float4 h = r4[k];
        a0 += w.x * h.x; a1 += w.y * h.y; a2 += w.z * h.z; a3 += w.w * h.w;
    }
    g_X[t * TMP + j] = (a0 + a1) + (a2 + a3) + b1[j];
}

// ---------------------------------------------------------------------------
// Phase 1b: C[e][j] = dot(emb_table[e, :], W1[j, 256:272])
// ---------------------------------------------------------------------------
__global__ void __launch_bounds__(128) c_kernel(const float* __restrict__ emb,
                                                const float* __restrict__ W1) {
    __shared__ __align__(16) float e[EMB];
    const int ei = blockIdx.x;
    const int j  = threadIdx.x;
    if (j < EMB) e[j] = emb[ei * EMB + j];
    __syncthreads();

    const float4* w4 = reinterpret_cast<const float4*>(W1 + j * (HID + EMB) + HID);
    const float4* e4 = reinterpret_cast<const float4*>(e);
    float a = 0.f;
#pragma unroll
    for (int k = 0; k < EMB / 4; k++) {
        float4 w = w4[k];
        float4 h = e4[k];
        a += w.x * h.x + w.y * h.y + w.z * h.z + w.w * h.w;
    }
    g_C[ei * TMP + j] = a;
}

// ---------------------------------------------------------------------------
// Phase 2: sequential greedy decode. Cluster of 8 CTAs x 256 threads.
// Packed f32x2 GEMV. Argmax exchange: every CTA pushes its candidate to ALL
// ranks with one st.async each (remote store + remote mbarrier complete_tx);
// each CTA waits its LOCAL mbarrier (acquire.cta) and reduces locally.
// ---------------------------------------------------------------------------
__global__ void __cluster_dims__(NCTA, 1, 1) __launch_bounds__(256, 1)
seq_kernel(const float* __restrict__ W2, const float* __restrict__ b2,
           const int* __restrict__ initp) {
    __shared__ __align__(16) float sh_h[TMP];
    __shared__ unsigned long long sh_warp[8];
    __shared__ __align__(8) unsigned long long cand[2][NCTA];  // [step parity][source rank]
    __shared__ __align__(8) unsigned long long mbar[2];        // double-buffered mbarriers
    __shared__ int sh_bcast;

    unsigned rank;
    asm("mov.u32 %0, %%cluster_ctarank;" : "=r"(rank));
    const int tid  = threadIdx.x;
    const int lane = tid & 31;
    const int wid  = tid >> 5;
    const int r    = (int)rank * 256 + tid;   // this thread's logit row

    // Pin W2 row as 64 packed f32x2 registers + bias.
    unsigned long long w[TMP / 2];
    const unsigned long long* wp =
        reinterpret_cast<const unsigned long long*>(W2 + (size_t)r * TMP);
#pragma unroll
    for (int k = 0; k < TMP / 2; k++) w[k] = wp[k];
    const float bias = b2[r];

    if (tid == 0) {
        unsigned m0 = (unsigned)__cvta_generic_to_shared(&mbar[0]);
        unsigned m1 = (unsigned)__cvta_generic_to_shared(&mbar[1]);
        // arrive count 1: tid0's arrive.expect_tx each phase; completion gated on tx bytes.
        asm volatile("mbarrier.init.shared.b64 [%0], %1;" :: "r"(m0), "r"(1) : "memory");
        asm volatile("mbarrier.init.shared.b64 [%0], %1;" :: "r"(m1), "r"(1) : "memory");
        asm volatile("fence.mbarrier_init.release.cluster;" ::: "memory");
    }
    __syncthreads();
    asm volatile("barrier.cluster.arrive.aligned;" ::: "memory");
    asm volatile("barrier.cluster.wait.aligned;" ::: "memory");

    int idx = *initp;
    float xv = (tid < TMP) ? g_X[tid] : 0.f;

    for (int t = 0; t < T_LEN; t++) {
        // h = leaky(X[t] + C[idx])
        if (tid < TMP) {
            float v = xv + g_C[idx * TMP + tid];
            sh_h[tid] = (v > 0.f) ? v : NEG_SLOPE * v;
        }
        // prefetch next X row (idx-independent)
        float xn = 0.f;
        if (tid < TMP && t + 1 < T_LEN) xn = g_X[(t + 1) * TMP + tid];
        __syncthreads();

        // GEMV: logit = W2[r] . h + b2[r]  (packed f32x2, 4 independent chains)
        const ulonglong2* h16 = reinterpret_cast<const ulonglong2*>(sh_h);
        unsigned long long a0 = 0ull, a1 = 0ull, a2 = 0ull, a3 = 0ull;
#pragma unroll
        for (int k = 0; k < 32; k += 2) {
            ulonglong2 hA = h16[k];
            ulonglong2 hB = h16[k + 1];
            a0 = fma2(w[2 * k + 0], hA.x, a0);
            a1 = fma2(w[2 * k + 1], hA.y, a1);
            a2 = fma2(w[2 * k + 2], hB.x, a2);
            a3 = fma2(w[2 * k + 3], hB.y, a3);
        }
        float2 f0 = unpack2(a0), f1 = unpack2(a1), f2v = unpack2(a2), f3 = unpack2(a3);
        const float acc = bias + (((f0.x + f0.y) + (f1.x + f1.y)) +
                                  ((f2v.x + f2v.y) + (f3.x + f3.y)));

        // warp argmax: monotone float->uint key; tie -> lowest global row
        unsigned key = __float_as_uint(acc);
        key ^= (key & 0x80000000u) ? 0xFFFFFFFFu : 0x80000000u;
        const unsigned wmax = __reduce_max_sync(0xFFFFFFFFu, key);
        const unsigned ball = __ballot_sync(0xFFFFFFFFu, key == wmax);
        if (lane == 0) {
            const int rwin = (int)rank * 256 + wid * 32 + (__ffs(ball) - 1);
            sh_warp[wid] = ((unsigned long long)wmax << 32) | (unsigned)(2047 - rwin);
        }
        __syncthreads();

        const int p  = t & 1;
        const int ph = (t >> 1) & 1;
        if (wid == 0) {
            // CTA-level reduce across the 8 warp candidates
            unsigned long long v = (lane < 8) ? sh_warp[lane] : 0ull;
            { unsigned long long o = __shfl_xor_sync(0xFFFFFFFFu, v, 4); v = (o > v) ? o : v; }
            { unsigned long long o = __shfl_xor_sync(0xFFFFFFFFu, v, 2); v = (o > v) ? o : v; }
            { unsigned long long o = __shfl_xor_sync(0xFFFFFFFFu, v, 1); v = (o > v) ? o : v; }

            // post this CTA's expectation for the incoming 8 candidates (64 bytes)
            if (lane == 0) {
                unsigned lm = (unsigned)__cvta_generic_to_shared(&mbar[p]);
                asm volatile("mbarrier.arrive.expect_tx.shared.b64 _, [%0], %1;"
                             :: "r"(lm), "r"(NCTA * 8) : "memory");
            }

            // push candidate to every rank's cand[p][myrank]: ONE st.async each
            // (remote store whose completion bumps the remote mbarrier tx-count)
            if (lane < NCTA) {
                unsigned lc = (unsigned)__cvta_generic_to_shared(&cand[p][rank]);
                unsigned lm = (unsigned)__cvta_generic_to_shared(&mbar[p]);
                unsigned rc, rm;
                asm("mapa.shared::cluster.u32 %0, %1, %2;" : "=r"(rc) : "r"(lc), "r"(lane));
                asm("mapa.shared::cluster.u32 %0, %1, %2;" : "=r"(rm) : "r"(lm), "r"(lane));
                asm volatile(
                    "st.async.weak.shared::cluster.mbarrier::complete_tx::bytes.b64 [%0], %1, [%2];"
                    :: "r"(rc), "l"(v), "r"(rm) : "memory");
            }

            // wait local mbar[p] (cta-scope acquire, TMA-consumer pattern)
            {
                unsigned lm = (unsigned)__cvta_generic_to_shared(&mbar[p]);
                asm volatile(
                    "{\n\t.reg .pred P1;\n\t"
                    "LW%=:\n\t"
                    "mbarrier.try_wait.parity.acquire.cta.shared::cta.b64 P1, [%0], %1, 0x989680;\n\t"
                    "@P1 bra.uni LD%=;\n\t"
                    "bra.uni LW%=;\n\t"
                    "LD%=:\n\t}"
                    :: "r"(lm), "r"(ph) : "memory");
            }

            // reduce the 8 received candidates locally
            unsigned long long c = (lane < 8) ? cand[p][lane] : 0ull;
            { unsigned long long o = __shfl_xor_sync(0xFFFFFFFFu, c, 4); c = (o > c) ? o : c; }
            { unsigned long long o = __shfl_xor_sync(0xFFFFFFFFu, c, 2); c = (o > c) ? o : c; }
            { unsigned long long o = __shfl_xor_sync(0xFFFFFFFFu, c, 1); c = (o > c) ? o : c; }
            if (lane == 0) {
                const int win = 2047 - (int)(c & 0xFFFFFFFFull);
                sh_bcast = win;
                if (rank == 0) g_idx[t] = win;
            }
        }
        __syncthreads();
        idx = sh_bcast;
        xv  = xn;
    }
}

// ---------------------------------------------------------------------------
// Phase 3: recompute logits for all t (8 rows per CTA, 4 cols per thread,
// packed f32x2), log_softmax, write all three outputs:
// [T*2048 log_probs | T*16 emb | T index-as-float].
// ---------------------------------------------------------------------------
__global__ void __launch_bounds__(512) out_kernel(const float* __restrict__ W2,
                                                  const float* __restrict__ b2,
                                                  const float* __restrict__ emb,
                                                  const int* __restrict__ initp,
                                                  float* __restrict__ out) {
    __shared__ __align__(16) float sh_h[8][TMP];
    __shared__ float red[16];
    const int t0  = blockIdx.x * 8;
    const int tid = threadIdx.x;
    const int lane = tid & 31;
    const int wid  = tid >> 5;

    // rebuild h rows exactly as in seq_kernel
    for (int q = tid; q < 8 * TMP; q += 512) {
        const int rr = q >> 7, j = q & 127;
        const int t = t0 + rr;
        const int in_idx = (t == 0) ? *initp : g_idx[t - 1];
        float v = g_X[t * TMP + j] + g_C[in_idx * TMP + j];
        sh_h[rr][j] = (v > 0.f) ? v : NEG_SLOPE * v;
    }
    __syncthreads();

    unsigned long long acc[8][4];
#pragma unroll
    for (int rr = 0; rr < 8; rr++)
#pragma unroll
        for (int cj = 0; cj < 4; cj++) acc[rr][cj] = 0ull;

    const ulonglong2* W16 = reinterpret_cast<const ulonglong2*>(W2);
#pragma unroll 2
    for (int k = 0; k < 32; k++) {
        ulonglong2 hh[8];
#pragma unroll
        for (int rr = 0; rr < 8; rr++)
            hh[rr] = reinterpret_cast<const ulonglong2*>(sh_h[rr])[k];
#pragma unroll
        for (int cj = 0; cj < 4; cj++) {
            const int c = tid + 512 * cj;
            const ulonglong2 wv = W16[(size_t)c * 32 + k];
#pragma unroll
            for (int rr = 0; rr < 8; rr++) {
                acc[rr][cj] = fma2(wv.x, hh[rr].x, acc[rr][cj]);
                acc[rr][cj] = fma2(wv.y, hh[rr].y, acc[rr][cj]);
            }
        }
    }

    float logit[8][4];
#pragma unroll
    for (int cj = 0; cj < 4; cj++) {
        const float b = b2[tid + 512 * cj];
#pragma unroll
        for (int rr = 0; rr < 8; rr++) {
            float2 f = unpack2(acc[rr][cj]);
            logit[rr][cj] = f.x + f.y + b;
        }
    }

    // log_softmax per row, then write
    for (int rr = 0; rr < 8; rr++) {
        float m = logit[rr][0];
#pragma unroll
        for (int cj = 1; cj < 4; cj++) m = fmaxf(m, logit[rr][cj]);
#pragma unroll
        for (int o = 16; o > 0; o >>= 1) m = fmaxf(m, __shfl_xor_sync(0xFFFFFFFFu, m, o));
        if (lane == 0) red[wid] = m;
        __syncthreads();
        float M = red[0];
#pragma unroll
        for (int i = 1; i < 16; i++) M = fmaxf(M, red[i]);
        __syncthreads();

        float s = 0.f;
#pragma unroll
        for (int cj = 0; cj < 4; cj++) s += __expf(logit[rr][cj] - M);
#pragma unroll
        for (int o = 16; o > 0; o >>= 1) s += __shfl_xor_sync(0xFFFFFFFFu, s, o);
        if (lane == 0) red[wid] = s;
        __syncthreads();
        float S = 0.f;
#pragma unroll
        for (int i = 0; i < 16; i++) S += red[i];
        __syncthreads();

        const float lse = M + __logf(S);
        const int t = t0 + rr;
#pragma unroll
        for (int cj = 0; cj < 4; cj++)
            out[(size_t)t * EVD + tid + 512 * cj] = logit[rr][cj] - lse;
    }

    // ner_emb and ner_index outputs
    float* out_emb = out + (size_t)T_LEN * EVD;
    float* out_idx = out_emb + (size_t)T_LEN * EMB;
    if (tid < 8 * EMB) {
        const int rr = tid >> 4, j = tid & 15;
        const int t = t0 + rr;
        out_emb[t * EMB + j] = emb[g_idx[t] * EMB + j];
    }
    if (tid < 8) {
        const int t = t0 + tid;
        out_idx[t] = (float)g_idx[t];
    }
}

// ---------------------------------------------------------------------------
extern "C" void kernel_launch(void* const* d_in, const int* in_sizes, int n_in,
                              void* d_out, int out_size) {
    const float* bilstm = (const float*)d_in[0];
    const float* emb    = (const float*)d_in[1];
    const float* W1     = (const float*)d_in[2];
    const float* b1     = (const float*)d_in[3];
    const float* W2     = (const float*)d_in[4];
    const float* b2     = (const float*)d_in[5];
    const int*   init   = (const int*)d_in[6];
    float* out = (float*)d_out;

    x_kernel<<<T_LEN, 128>>>(bilstm, W1, b1);
    c_kernel<<<EVD, 128>>>(emb, W1);
    seq_kernel<<<NCTA, 256>>>(W2, b2, init);
    out_kernel<<<T_LEN / 8, 512>>>(W2, b2, emb, init, out);
}

// round 4
// speedup vs baseline: 1.9506x; 1.2870x over previous
#include <cuda_runtime.h>
#include <cstdint>

#define T_LEN 16384
#define HID   256
#define EMB   16
#define TMP   128
#define EVD   2048
#define NCTA  8
#define NEG_SLOPE 0.01f

// Scratch (static device globals — no allocation at runtime)
__device__ float g_X[T_LEN * TMP];   // 8 MB: bilstm part of layer-1 preactivation (incl. b1)
__device__ float g_C[EVD * TMP];     // 1 MB: event-embedding part of layer-1 preactivation
__device__ int   g_idx[T_LEN];       // argmax index emitted at each step

// Packed fp32x2 FMA (sm_100+): d = a*b + c elementwise on two packed floats.
__device__ __forceinline__ unsigned long long fma2(unsigned long long a,
                                                   unsigned long long b,
                                                   unsigned long long c) {
    unsigned long long d;
    asm("fma.rn.f32x2 %0, %1, %2, %3;" : "=l"(d) : "l"(a), "l"(b), "l"(c));
    return d;
}
__device__ __forceinline__ float2 unpack2(unsigned long long v) {
    float2 r;
    asm("mov.b64 {%0, %1}, %2;" : "=f"(r.x), "=f"(r.y) : "l"(v));
    return r;
}

// ---------------------------------------------------------------------------
// Phase 1a: X[t][j] for 8 timesteps per CTA (W1 row read once per 8 rows).
// ---------------------------------------------------------------------------
__global__ void __launch_bounds__(128) x_kernel(const float* __restrict__ bilstm,
                                                const float* __restrict__ W1,
                                                const float* __restrict__ b1) {
    __shared__ __align__(16) float rows[8][HID];
    const int t0 = blockIdx.x * 8;
    const int j  = threadIdx.x;

    for (int q = j; q < 8 * HID; q += 128) {
        rows[q >> 8][q & 255] = bilstm[t0 * HID + q];
    }
    __syncthreads();

    const float4* w4 = reinterpret_cast<const float4*>(W1 + j * (HID + EMB));
    float acc[8];
    const float bb = b1[j];
#pragma unroll
    for (int rr = 0; rr < 8; rr++) acc[rr] = bb;

#pragma unroll 8
    for (int k = 0; k < HID / 4; k++) {
        const float4 w = w4[k];
#pragma unroll
        for (int rr = 0; rr < 8; rr++) {
            const float4 h = reinterpret_cast<const float4*>(rows[rr])[k];
            acc[rr] += w.x * h.x + w.y * h.y + w.z * h.z + w.w * h.w;
        }
    }
#pragma unroll
    for (int rr = 0; rr < 8; rr++)
        g_X[(t0 + rr) * TMP + j] = acc[rr];
}

// ---------------------------------------------------------------------------
// Phase 1b: C[e][j] = dot(emb_table[e, :], W1[j, 256:272])
// ---------------------------------------------------------------------------
__global__ void __launch_bounds__(128) c_kernel(const float* __restrict__ emb,
                                                const float* __restrict__ W1) {
    __shared__ __align__(16) float e[EMB];
    const int ei = blockIdx.x;
    const int j  = threadIdx.x;
    if (j < EMB) e[j] = emb[ei * EMB + j];
    __syncthreads();

    const float4* w4 = reinterpret_cast<const float4*>(W1 + j * (HID + EMB) + HID);
    const float4* e4 = reinterpret_cast<const float4*>(e);
    float a = 0.f;
#pragma unroll
    for (int k = 0; k < EMB / 4; k++) {
        float4 w = w4[k];
        float4 h = e4[k];
        a += w.x * h.x + w.y * h.y + w.z * h.z + w.w * h.w;
    }
    g_C[ei * TMP + j] = a;
}

// ---------------------------------------------------------------------------
// Phase 2: sequential greedy decode. Cluster of 8 CTAs x 256 threads.
// ONE __syncthreads per step. Every warp pushes its own candidate to all 8
// ranks (64-slot buffer); every warp waits the local mbarrier and reduces
// the 64 candidates itself (dual REDUX) — no tail barrier, no broadcast.
// ---------------------------------------------------------------------------
__global__ void __cluster_dims__(NCTA, 1, 1) __launch_bounds__(256, 1)
seq_kernel(const float* __restrict__ W2, const float* __restrict__ b2,
           const int* __restrict__ initp) {
    __shared__ __align__(16) float sh_h[TMP];
    __shared__ __align__(8) unsigned long long cand[2][NCTA * 8];  // [parity][src_rank*8+src_wid]
    __shared__ __align__(8) unsigned long long mbar[2];            // double-buffered mbarriers

    unsigned rank;
    asm("mov.u32 %0, %%cluster_ctarank;" : "=r"(rank));
    const int tid  = threadIdx.x;
    const int lane = tid & 31;
    const int wid  = tid >> 5;
    const int r    = (int)rank * 256 + tid;   // this thread's logit row
    const unsigned irow = 2047u - (unsigned)r; // inverted row (max => lowest row)

    // Pin W2 row as 64 packed f32x2 registers + bias.
    unsigned long long w[TMP / 2];
    const unsigned long long* wp =
        reinterpret_cast<const unsigned long long*>(W2 + (size_t)r * TMP);
#pragma unroll
    for (int k = 0; k < TMP / 2; k++) w[k] = wp[k];
    const float bias = b2[r];

    if (tid == 0) {
        unsigned m0 = (unsigned)__cvta_generic_to_shared(&mbar[0]);
        unsigned m1 = (unsigned)__cvta_generic_to_shared(&mbar[1]);
        // arrive count 1: tid0's arrive.expect_tx each phase; completion gated on tx bytes.
        asm volatile("mbarrier.init.shared.b64 [%0], %1;" :: "r"(m0), "r"(1) : "memory");
        asm volatile("mbarrier.init.shared.b64 [%0], %1;" :: "r"(m1), "r"(1) : "memory");
        asm volatile("fence.mbarrier_init.release.cluster;" ::: "memory");
    }
    __syncthreads();
    asm volatile("barrier.cluster.arrive.aligned;" ::: "memory");
    asm volatile("barrier.cluster.wait.aligned;" ::: "memory");

    int idx = *initp;
    float xv = (tid < TMP) ? g_X[tid] : 0.f;

    for (int t = 0; t < T_LEN; t++) {
        const int p  = t & 1;
        const int ph = (t >> 1) & 1;

        // h = leaky(X[t] + C[idx])
        if (tid < TMP) {
            float v = xv + g_C[idx * TMP + tid];
            sh_h[tid] = (v > 0.f) ? v : NEG_SLOPE * v;
        }
        // prefetch next X row (idx-independent)
        float xn = 0.f;
        if (tid < TMP && t + 1 < T_LEN) xn = g_X[(t + 1) * TMP + tid];
        __syncthreads();   // h visible to all warps (the ONLY per-step barrier)

        // post expectation for this step's 64 incoming candidates (512 bytes)
        if (tid == 0) {
            unsigned lm = (unsigned)__cvta_generic_to_shared(&mbar[p]);
            asm volatile("mbarrier.arrive.expect_tx.shared.b64 _, [%0], %1;"
                         :: "r"(lm), "r"(NCTA * 8 * 8) : "memory");
        }

        // GEMV: logit = W2[r] . h + b2[r]  (packed f32x2, 4 independent chains)
        const ulonglong2* h16 = reinterpret_cast<const ulonglong2*>(sh_h);
        unsigned long long a0 = 0ull, a1 = 0ull, a2 = 0ull, a3 = 0ull;
#pragma unroll
        for (int k = 0; k < 32; k += 2) {
            ulonglong2 hA = h16[k];
            ulonglong2 hB = h16[k + 1];
            a0 = fma2(w[2 * k + 0], hA.x, a0);
            a1 = fma2(w[2 * k + 1], hA.y, a1);
            a2 = fma2(w[2 * k + 2], hB.x, a2);
            a3 = fma2(w[2 * k + 3], hB.y, a3);
        }
        float2 f0 = unpack2(a0), f1 = unpack2(a1), f2v = unpack2(a2), f3 = unpack2(a3);
        const float acc = bias + (((f0.x + f0.y) + (f1.x + f1.y)) +
                                  ((f2v.x + f2v.y) + (f3.x + f3.y)));

        // warp argmax via dual REDUX: max key, then max inverted-row among key-winners
        unsigned key = __float_as_uint(acc);
        key ^= (key & 0x80000000u) ? 0xFFFFFFFFu : 0x80000000u;
        const unsigned kmax  = __reduce_max_sync(0xFFFFFFFFu, key);
        const unsigned wirow = __reduce_max_sync(0xFFFFFFFFu, (key == kmax) ? irow : 0u);
        const unsigned long long v = ((unsigned long long)kmax << 32) | wirow;

        // every warp pushes its candidate to ALL ranks: lanes 0-7, one st.async each
        if (lane < NCTA) {
            unsigned lc = (unsigned)__cvta_generic_to_shared(&cand[p][rank * 8 + wid]);
            unsigned lm = (unsigned)__cvta_generic_to_shared(&mbar[p]);
            unsigned rc, rm;
            asm("mapa.shared::cluster.u32 %0, %1, %2;" : "=r"(rc) : "r"(lc), "r"(lane));
            asm("mapa.shared::cluster.u32 %0, %1, %2;" : "=r"(rm) : "r"(lm), "r"(lane));
            asm volatile(
                "st.async.weak.shared::cluster.mbarrier::complete_tx::bytes.b64 [%0], %1, [%2];"
                :: "r"(rc), "l"(v), "r"(rm) : "memory");
        }

        // every warp waits the LOCAL mbarrier (cta-scope acquire)
        {
            unsigned lm = (unsigned)__cvta_generic_to_shared(&mbar[p]);
            asm volatile(
                "{\n\t.reg .pred P1;\n\t"
                "LW%=:\n\t"
                "mbarrier.try_wait.parity.acquire.cta.shared::cta.b64 P1, [%0], %1, 0x989680;\n\t"
                "@P1 bra.uni LD%=;\n\t"
                "bra.uni LW%=;\n\t"
                "LD%=:\n\t}"
                :: "r"(lm), "r"(ph) : "memory");
        }

        // every warp reduces the 64 candidates itself: 2 LDS + local max + dual REDUX
        {
            const unsigned long long ca = cand[p][lane];
            const unsigned long long cb = cand[p][lane + 32];
            const unsigned long long lv = (ca > cb) ? ca : cb;
            const unsigned hi = (unsigned)(lv >> 32);
            const unsigned lo = (unsigned)lv;
            const unsigned hmax = __reduce_max_sync(0xFFFFFFFFu, hi);
            const unsigned lmax = __reduce_max_sync(0xFFFFFFFFu, (hi == hmax) ? lo : 0u);
            idx = 2047 - (int)lmax;
        }
        if (rank == 0 && tid == 0) g_idx[t] = idx;
        xv = xn;
        // NOTE: no tail barrier. mbar completion implies every warp's GEMV
        // reads of sh_h finished (their st.async is data-dependent on them),
        // so warps 0-3 may safely overwrite sh_h next iteration.
    }
}

// ---------------------------------------------------------------------------
// Phase 3: recompute logits for all t (8 rows per CTA, 4 cols per thread,
// packed f32x2), log_softmax, write all three outputs:
// [T*2048 log_probs | T*16 emb | T index-as-float].
// ---------------------------------------------------------------------------
__global__ void __launch_bounds__(512) out_kernel(const float* __restrict__ W2,
                                                  const float* __restrict__ b2,
                                                  const float* __restrict__ emb,
                                                  const int* __restrict__ initp,
                                                  float* __restrict__ out) {
    __shared__ __align__(16) float sh_h[8][TMP];
    __shared__ float red[16];
    const int t0  = blockIdx.x * 8;
    const int tid = threadIdx.x;
    const int lane = tid & 31;
    const int wid  = tid >> 5;

    // rebuild h rows exactly as in seq_kernel
    for (int q = tid; q < 8 * TMP; q += 512) {
        const int rr = q >> 7, j = q & 127;
        const int t = t0 + rr;
        const int in_idx = (t == 0) ? *initp : g_idx[t - 1];
        float v = g_X[t * TMP + j] + g_C[in_idx * TMP + j];
        sh_h[rr][j] = (v > 0.f) ? v : NEG_SLOPE * v;
    }
    __syncthreads();

    unsigned long long acc[8][4];
#pragma unroll
    for (int rr = 0; rr < 8; rr++)
#pragma unroll
        for (int cj = 0; cj < 4; cj++) acc[rr][cj] = 0ull;

    const ulonglong2* W16 = reinterpret_cast<const ulonglong2*>(W2);
#pragma unroll 2
    for (int k = 0; k < 32; k++) {
        ulonglong2 hh[8];
#pragma unroll
        for (int rr = 0; rr < 8; rr++)
            hh[rr] = reinterpret_cast<const ulonglong2*>(sh_h[rr])[k];
#pragma unroll
        for (int cj = 0; cj < 4; cj++) {
            const int c = tid + 512 * cj;
            const ulonglong2 wv = W16[(size_t)c * 32 + k];
#pragma unroll
            for (int rr = 0; rr < 8; rr++) {
                acc[rr][cj] = fma2(wv.x, hh[rr].x, acc[rr][cj]);
                acc[rr][cj] = fma2(wv.y, hh[rr].y, acc[rr][cj]);
            }
        }
    }

    float logit[8][4];
#pragma unroll
    for (int cj = 0; cj < 4; cj++) {
        const float b = b2[tid + 512 * cj];
#pragma unroll
        for (int rr = 0; rr < 8; rr++) {
            float2 f = unpack2(acc[rr][cj]);
            logit[rr][cj] = f.x + f.y + b;
        }
    }

    // log_softmax per row, then write
    for (int rr = 0; rr < 8; rr++) {
        float m = logit[rr][0];
#pragma unroll
        for (int cj = 1; cj < 4; cj++) m = fmaxf(m, logit[rr][cj]);
#pragma unroll
        for (int o = 16; o > 0; o >>= 1) m = fmaxf(m, __shfl_xor_sync(0xFFFFFFFFu, m, o));
        if (lane == 0) red[wid] = m;
        __syncthreads();
        float M = red[0];
#pragma unroll
        for (int i = 1; i < 16; i++) M = fmaxf(M, red[i]);
        __syncthreads();

        float s = 0.f;
#pragma unroll
        for (int cj = 0; cj < 4; cj++) s += __expf(logit[rr][cj] - M);
#pragma unroll
        for (int o = 16; o > 0; o >>= 1) s += __shfl_xor_sync(0xFFFFFFFFu, s, o);
        if (lane == 0) red[wid] = s;
        __syncthreads();
        float S = 0.f;
#pragma unroll
        for (int i = 0; i < 16; i++) S += red[i];
        __syncthreads();

        const float lse = M + __logf(S);
        const int t = t0 + rr;
#pragma unroll
        for (int cj = 0; cj < 4; cj++)
            out[(size_t)t * EVD + tid + 512 * cj] = logit[rr][cj] - lse;
    }

    // ner_emb and ner_index outputs
    float* out_emb = out + (size_t)T_LEN * EVD;
    float* out_idx = out_emb + (size_t)T_LEN * EMB;
    if (tid < 8 * EMB) {
        const int rr = tid >> 4, j = tid & 15;
        const int t = t0 + rr;
        out_emb[t * EMB + j] = emb[g_idx[t] * EMB + j];
    }
    if (tid < 8) {
        const int t = t0 + tid;
        out_idx[t] = (float)g_idx[t];
    }
}

// ---------------------------------------------------------------------------
extern "C" void kernel_launch(void* const* d_in, const int* in_sizes, int n_in,
                              void* d_out, int out_size) {
    const float* bilstm = (const float*)d_in[0];
    const float* emb    = (const float*)d_in[1];
    const float* W1     = (const float*)d_in[2];
    const float* b1     = (const float*)d_in[3];
    const float* W2     = (const float*)d_in[4];
    const float* b2     = (const float*)d_in[5];
    const int*   init   = (const int*)d_in[6];
    float* out = (float*)d_out;

    x_kernel<<<T_LEN / 8, 128>>>(bilstm, W1, b1);
    c_kernel<<<EVD, 128>>>(emb, W1);
    seq_kernel<<<NCTA, 256>>>(W2, b2, init);
    out_kernel<<<T_LEN / 8, 512>>>(W2, b2, emb, init, out);
}

// round 5
// speedup vs baseline: 2.1947x; 1.1252x over previous
#include <cuda_runtime.h>
#include <cstdint>

#define T_LEN 16384
#define HID   256
#define EMB   16
#define TMP   128
#define EVD   2048
#define NCTA  16          // 16-CTA cluster (non-portable size, enabled at launch)
#define NTHR  128         // threads per CTA; NCTA*NTHR = 2048 = one thread per logit row
#define NEG_SLOPE 0.01f

// Scratch (static device globals — no allocation at runtime)
__device__ float g_X[T_LEN * TMP];   // 8 MB: bilstm part of layer-1 preactivation (incl. b1)
__device__ float g_C[EVD * TMP];     // 1 MB: event-embedding part of layer-1 preactivation
__device__ int   g_idx[T_LEN];       // argmax index emitted at each step

// Packed fp32x2 FMA (sm_100+): d = a*b + c elementwise on two packed floats.
__device__ __forceinline__ unsigned long long fma2(unsigned long long a,
                                                   unsigned long long b,
                                                   unsigned long long c) {
    unsigned long long d;
    asm("fma.rn.f32x2 %0, %1, %2, %3;" : "=l"(d) : "l"(a), "l"(b), "l"(c));
    return d;
}
__device__ __forceinline__ float2 unpack2(unsigned long long v) {
    float2 r;
    asm("mov.b64 {%0, %1}, %2;" : "=f"(r.x), "=f"(r.y) : "l"(v));
    return r;
}

// ---------------------------------------------------------------------------
// Phase 1a: X[t][j] for 8 timesteps per CTA (W1 row read once per 8 rows).
// ---------------------------------------------------------------------------
__global__ void __launch_bounds__(128) x_kernel(const float* __restrict__ bilstm,
                                                const float* __restrict__ W1,
                                                const float* __restrict__ b1) {
    __shared__ __align__(16) float rows[8][HID];
    const int t0 = blockIdx.x * 8;
    const int j  = threadIdx.x;

    for (int q = j; q < 8 * HID; q += 128) {
        rows[q >> 8][q & 255] = bilstm[t0 * HID + q];
    }
    __syncthreads();

    const float4* w4 = reinterpret_cast<const float4*>(W1 + j * (HID + EMB));
    float acc[8];
    const float bb = b1[j];
#pragma unroll
    for (int rr = 0; rr < 8; rr++) acc[rr] = bb;

#pragma unroll 8
    for (int k = 0; k < HID / 4; k++) {
        const float4 w = w4[k];
#pragma unroll
        for (int rr = 0; rr < 8; rr++) {
            const float4 h = reinterpret_cast<const float4*>(rows[rr])[k];
            acc[rr] += w.x * h.x + w.y * h.y + w.z * h.z + w.w * h.w;
        }
    }
#pragma unroll
    for (int rr = 0; rr < 8; rr++)
        g_X[(t0 + rr) * TMP + j] = acc[rr];
}

// ---------------------------------------------------------------------------
// Phase 1b: C[e][j] = dot(emb_table[e, :], W1[j, 256:272])
// ---------------------------------------------------------------------------
__global__ void __launch_bounds__(128) c_kernel(const float* __restrict__ emb,
                                                const float* __restrict__ W1) {
    __shared__ __align__(16) float e[EMB];
    const int ei = blockIdx.x;
    const int j  = threadIdx.x;
    if (j < EMB) e[j] = emb[ei * EMB + j];
    __syncthreads();

    const float4* w4 = reinterpret_cast<const float4*>(W1 + j * (HID + EMB) + HID);
    const float4* e4 = reinterpret_cast<const float4*>(e);
    float a = 0.f;
#pragma unroll
    for (int k = 0; k < EMB / 4; k++) {
        float4 w = w4[k];
        float4 h = e4[k];
        a += w.x * h.x + w.y * h.y + w.z * h.z + w.w * h.w;
    }
    g_C[ei * TMP + j] = a;
}

// ---------------------------------------------------------------------------
// Phase 2: sequential greedy decode. Cluster of 16 CTAs x 128 threads
// (1 warp/SMSP -> minimal GEMV issue time). ONE __syncthreads per step.
// Every warp pushes its candidate to ALL 16 ranks (64-slot buffer = 16x4);
// every warp waits the local mbarrier and reduces the 64 candidates itself.
// ---------------------------------------------------------------------------
__global__ void __cluster_dims__(NCTA, 1, 1) __launch_bounds__(NTHR, 1)
seq_kernel(const float* __restrict__ W2, const float* __restrict__ b2,
           const int* __restrict__ initp) {
    __shared__ __align__(16) float sh_h[TMP];
    __shared__ __align__(8) unsigned long long cand[2][64];  // [parity][src_rank*4+src_wid]
    __shared__ __align__(8) unsigned long long mbar[2];      // double-buffered mbarriers

    unsigned rank;
    asm("mov.u32 %0, %%cluster_ctarank;" : "=r"(rank));
    const int tid  = threadIdx.x;
    const int lane = tid & 31;
    const int wid  = tid >> 5;
    const int r    = (int)rank * NTHR + tid;   // this thread's logit row
    const unsigned irow = 2047u - (unsigned)r; // inverted row (max => lowest row)

    // Pin W2 row as 64 packed f32x2 registers + bias.
    unsigned long long w[TMP / 2];
    const unsigned long long* wp =
        reinterpret_cast<const unsigned long long*>(W2 + (size_t)r * TMP);
#pragma unroll
    for (int k = 0; k < TMP / 2; k++) w[k] = wp[k];
    const float bias = b2[r];

    if (tid == 0) {
        unsigned m0 = (unsigned)__cvta_generic_to_shared(&mbar[0]);
        unsigned m1 = (unsigned)__cvta_generic_to_shared(&mbar[1]);
        // arrive count 1: tid0's arrive.expect_tx each phase; completion gated on tx bytes.
        asm volatile("mbarrier.init.shared.b64 [%0], %1;" :: "r"(m0), "r"(1) : "memory");
        asm volatile("mbarrier.init.shared.b64 [%0], %1;" :: "r"(m1), "r"(1) : "memory");
        asm volatile("fence.mbarrier_init.release.cluster;" ::: "memory");
    }
    __syncthreads();
    asm volatile("barrier.cluster.arrive.aligned;" ::: "memory");
    asm volatile("barrier.cluster.wait.aligned;" ::: "memory");

    int idx = *initp;
    float xv = g_X[tid];

    for (int t = 0; t < T_LEN; t++) {
        const int p  = t & 1;
        const int ph = (t >> 1) & 1;

        // h = leaky(X[t] + C[idx])  (all 128 threads)
        {
            float v = xv + g_C[idx * TMP + tid];
            sh_h[tid] = (v > 0.f) ? v : NEG_SLOPE * v;
        }
        // prefetch next X row (idx-independent)
        float xn = 0.f;
        if (t + 1 < T_LEN) xn = g_X[(t + 1) * TMP + tid];
        __syncthreads();   // h visible to all warps (the ONLY per-step barrier)

        // post expectation for this step's 64 incoming candidates (512 bytes)
        if (tid == 0) {
            unsigned lm = (unsigned)__cvta_generic_to_shared(&mbar[p]);
            asm volatile("mbarrier.arrive.expect_tx.shared.b64 _, [%0], %1;"
                         :: "r"(lm), "r"(64 * 8) : "memory");
        }

        // GEMV: logit = W2[r] . h + b2[r]  (packed f32x2, 4 independent chains)
        const ulonglong2* h16 = reinterpret_cast<const ulonglong2*>(sh_h);
        unsigned long long a0 = 0ull, a1 = 0ull, a2 = 0ull, a3 = 0ull;
#pragma unroll
        for (int k = 0; k < 32; k += 2) {
            ulonglong2 hA = h16[k];
            ulonglong2 hB = h16[k + 1];
            a0 = fma2(w[2 * k + 0], hA.x, a0);
            a1 = fma2(w[2 * k + 1], hA.y, a1);
            a2 = fma2(w[2 * k + 2], hB.x, a2);
            a3 = fma2(w[2 * k + 3], hB.y, a3);
        }
        float2 f0 = unpack2(a0), f1 = unpack2(a1), f2v = unpack2(a2), f3 = unpack2(a3);
        const float acc = bias + (((f0.x + f0.y) + (f1.x + f1.y)) +
                                  ((f2v.x + f2v.y) + (f3.x + f3.y)));

        // warp argmax via dual REDUX: max key, then max inverted-row among key-winners
        unsigned key = __float_as_uint(acc);
        key ^= (key & 0x80000000u) ? 0xFFFFFFFFu : 0x80000000u;
        const unsigned kmax  = __reduce_max_sync(0xFFFFFFFFu, key);
        const unsigned wirow = __reduce_max_sync(0xFFFFFFFFu, (key == kmax) ? irow : 0u);
        const unsigned long long v = ((unsigned long long)kmax << 32) | wirow;

        // every warp pushes its candidate to ALL 16 ranks: lanes 0-15, one st.async each
        if (lane < NCTA) {
            unsigned lc = (unsigned)__cvta_generic_to_shared(&cand[p][rank * 4 + wid]);
            unsigned lm = (unsigned)__cvta_generic_to_shared(&mbar[p]);
            unsigned rc, rm;
            asm("mapa.shared::cluster.u32 %0, %1, %2;" : "=r"(rc) : "r"(lc), "r"(lane));
            asm("mapa.shared::cluster.u32 %0, %1, %2;" : "=r"(rm) : "r"(lm), "r"(lane));
            asm volatile(
                "st.async.weak.shared::cluster.mbarrier::complete_tx::bytes.b64 [%0], %1, [%2];"
                :: "r"(rc), "l"(v), "r"(rm) : "memory");
        }

        // every warp waits the LOCAL mbarrier (cta-scope acquire)
        {
            unsigned lm = (unsigned)__cvta_generic_to_shared(&mbar[p]);
            asm volatile(
                "{\n\t.reg .pred P1;\n\t"
                "LW%=:\n\t"
                "mbarrier.try_wait.parity.acquire.cta.shared::cta.b64 P1, [%0], %1, 0x989680;\n\t"
                "@P1 bra.uni LD%=;\n\t"
                "bra.uni LW%=;\n\t"
                "LD%=:\n\t}"
                :: "r"(lm), "r"(ph) : "memory");
        }

        // every warp reduces the 64 candidates itself: 2 LDS + local max + dual REDUX
        {
            const unsigned long long ca = cand[p][lane];
            const unsigned long long cb = cand[p][lane + 32];
            const unsigned long long lv = (ca > cb) ? ca : cb;
            const unsigned hi = (unsigned)(lv >> 32);
            const unsigned lo = (unsigned)lv;
            const unsigned hmax = __reduce_max_sync(0xFFFFFFFFu, hi);
            const unsigned lmax = __reduce_max_sync(0xFFFFFFFFu, (hi == hmax) ? lo : 0u);
            idx = 2047 - (int)lmax;
        }
        if (rank == 0 && tid == 0) g_idx[t] = idx;
        xv = xn;
        // NOTE: no tail barrier. mbar completion implies every warp's GEMV
        // reads of sh_h finished (their st.async is data-dependent on them),
        // so sh_h may be safely overwritten next iteration.
    }
}

// ---------------------------------------------------------------------------
// Phase 3: recompute logits for all t (8 rows per CTA, 4 cols per thread,
// packed f32x2), log_softmax, write all three outputs:
// [T*2048 log_probs | T*16 emb | T index-as-float].
// ---------------------------------------------------------------------------
__global__ void __launch_bounds__(512) out_kernel(const float* __restrict__ W2,
                                                  const float* __restrict__ b2,
                                                  const float* __restrict__ emb,
                                                  const int* __restrict__ initp,
                                                  float* __restrict__ out) {
    __shared__ __align__(16) float sh_h[8][TMP];
    __shared__ float red[16];
    const int t0  = blockIdx.x * 8;
    const int tid = threadIdx.x;
    const int lane = tid & 31;
    const int wid  = tid >> 5;

    // rebuild h rows exactly as in seq_kernel
    for (int q = tid; q < 8 * TMP; q += 512) {
        const int rr = q >> 7, j = q & 127;
        const int t = t0 + rr;
        const int in_idx = (t == 0) ? *initp : g_idx[t - 1];
        float v = g_X[t * TMP + j] + g_C[in_idx * TMP + j];
        sh_h[rr][j] = (v > 0.f) ? v : NEG_SLOPE * v;
    }
    __syncthreads();

    unsigned long long acc[8][4];
#pragma unroll
    for (int rr = 0; rr < 8; rr++)
#pragma unroll
        for (int cj = 0; cj < 4; cj++) acc[rr][cj] = 0ull;

    const ulonglong2* W16 = reinterpret_cast<const ulonglong2*>(W2);
#pragma unroll 2
    for (int k = 0; k < 32; k++) {
        ulonglong2 hh[8];
#pragma unroll
        for (int rr = 0; rr < 8; rr++)
            hh[rr] = reinterpret_cast<const ulonglong2*>(sh_h[rr])[k];
#pragma unroll
        for (int cj = 0; cj < 4; cj++) {
            const int c = tid + 512 * cj;
            const ulonglong2 wv = W16[(size_t)c * 32 + k];
#pragma unroll
            for (int rr = 0; rr < 8; rr++) {
                acc[rr][cj] = fma2(wv.x, hh[rr].x, acc[rr][cj]);
                acc[rr][cj] = fma2(wv.y, hh[rr].y, acc[rr][cj]);
            }
        }
    }

    float logit[8][4];
#pragma unroll
    for (int cj = 0; cj < 4; cj++) {
        const float b = b2[tid + 512 * cj];
#pragma unroll
        for (int rr = 0; rr < 8; rr++) {
            float2 f = unpack2(acc[rr][cj]);
            logit[rr][cj] = f.x + f.y + b;
        }
    }

    // log_softmax per row, then write
    for (int rr = 0; rr < 8; rr++) {
        float m = logit[rr][0];
#pragma unroll
        for (int cj = 1; cj < 4; cj++) m = fmaxf(m, logit[rr][cj]);
#pragma unroll
        for (int o = 16; o > 0; o >>= 1) m = fmaxf(m, __shfl_xor_sync(0xFFFFFFFFu, m, o));
        if (lane == 0) red[wid] = m;
        __syncthreads();
        float M = red[0];
#pragma unroll
        for (int i = 1; i < 16; i++) M = fmaxf(M, red[i]);
        __syncthreads();

        float s = 0.f;
#pragma unroll
        for (int cj = 0; cj < 4; cj++) s += __expf(logit[rr][cj] - M);
#pragma unroll
        for (int o = 16; o > 0; o >>= 1) s += __shfl_xor_sync(0xFFFFFFFFu, s, o);
        if (lane == 0) red[wid] = s;
        __syncthreads();
        float S = 0.f;
#pragma unroll
        for (int i = 0; i < 16; i++) S += red[i];
        __syncthreads();

        const float lse = M + __logf(S);
        const int t = t0 + rr;
#pragma unroll
        for (int cj = 0; cj < 4; cj++)
            out[(size_t)t * EVD + tid + 512 * cj] = logit[rr][cj] - lse;
    }

    // ner_emb and ner_index outputs
    float* out_emb = out + (size_t)T_LEN * EVD;
    float* out_idx = out_emb + (size_t)T_LEN * EMB;
    if (tid < 8 * EMB) {
        const int rr = tid >> 4, j = tid & 15;
        const int t = t0 + rr;
        out_emb[t * EMB + j] = emb[g_idx[t] * EMB + j];
    }
    if (tid < 8) {
        const int t = t0 + tid;
        out_idx[t] = (float)g_idx[t];
    }
}

// ---------------------------------------------------------------------------
extern "C" void kernel_launch(void* const* d_in, const int* in_sizes, int n_in,
                              void* d_out, int out_size) {
    const float* bilstm = (const float*)d_in[0];
    const float* emb    = (const float*)d_in[1];
    const float* W1     = (const float*)d_in[2];
    const float* b1     = (const float*)d_in[3];
    const float* W2     = (const float*)d_in[4];
    const float* b2     = (const float*)d_in[5];
    const int*   init   = (const int*)d_in[6];
    float* out = (float*)d_out;

    // Allow the 16-CTA (non-portable) cluster. Host-side attribute set:
    // executes immediately, not a stream op -> graph-capture safe, idempotent.
    cudaFuncSetAttribute((const void*)seq_kernel,
                         cudaFuncAttributeNonPortableClusterSizeAllowed, 1);

    x_kernel<<<T_LEN / 8, 128>>>(bilstm, W1, b1);
    c_kernel<<<EVD, 128>>>(emb, W1);
    seq_kernel<<<NCTA, NTHR>>>(W2, b2, init);
    out_kernel<<<T_LEN / 8, 512>>>(W2, b2, emb, init, out);
}